// round 2
// baseline (speedup 1.0000x reference)
#include <cuda_runtime.h>

// PLNet expansion: out[pp][n,k,i,j,y,x] =
//   0.5*cor0[ij]*cork[ij] * cen0[yx]*cenk[yx]
//   * cor[23+y][ij] * cor[37+x][ij] * cen[23+i][yx] * cen[37+j][yx]
// cor = corner(pp&1), cen = center(pp>>1). Input (n, 204, 14, 14):
// corner1 ch 0..50, corner2 51..101, center1 102..152, center2 153..203.
//
// Block: (k = bx, n = by, i-chunk of 7 = bz), 256 threads = 4 pp x 64 lanes.
// Warps are pp-pure (pp = t/64). Lane q (<49) owns an aligned float4 quad of
// the 196-element (y,x) plane. Cor-side operands come from ONE shared row of
// 28 floats per (i,j): lane l loads row[l] (1 wavefront), all lanes pick
// their w[y]/v[x] via __shfl_sync (no L1 crossbar traffic).

__global__ __launch_bounds__(256)
void plnet_kernel(const float* __restrict__ in, float* __restrict__ out)
{
    const int k   = blockIdx.x;        // 0..19
    const int n   = blockIdx.y;        // 0..31
    const int i0g = blockIdx.z * 7;    // i chunk start (0 or 7)
    const int t   = threadIdx.x;

    // R[cc][rij][c]: c<14 -> w[y]=0.5*cor0*cork*cor[23+y]; c>=14 -> v[x]=cor[37+(c-14)]
    // rij = local (i,j) row index 0..97; global plane index ij = i0g*14 + rij.
    __shared__ float R_s[2][98][29];
    __shared__ float a_s[2][98];

    const float* nb = in + n * (204 * 196);

    // ---- a = 0.5*cor0*cork per (cc, rij) ----
    if (t < 196) {
        const int cc  = t / 98;
        const int rij = t - cc * 98;
        const int ij  = i0g * 14 + rij;
        const float* cor = nb + cc * (51 * 196);
        a_s[cc][rij] = 0.5f * cor[ij] * cor[(1 + k) * 196 + ij];
    }
    __syncthreads();

    // ---- build R (rij fastest -> coalesced LDG; stride-29 STS conflict-free) ----
    for (int idx = t; idx < 2 * 98 * 28; idx += 256) {
        const int rij = idx % 98;
        const int r2  = idx / 98;
        const int c   = r2 % 28;
        const int cc  = r2 / 28;
        const int ij  = i0g * 14 + rij;
        const float* cor = nb + cc * (51 * 196);
        float val;
        if (c < 14) val = a_s[cc][rij] * cor[(23 + c) * 196 + ij];
        else        val = cor[(37 + (c - 14)) * 196 + ij];
        R_s[cc][rij][c] = val;
    }

    // ---- per-thread setup ----
    const int pp   = t >> 6;           // 0..3 (warp-pure: warp = 2*pp or 2*pp+1)
    const int lp   = t & 63;           // lane within pp group
    const bool act = (lp < 49);
    const int q    = act ? lp : 48;    // clamp idle lanes to valid addresses
    const int cc   = pp & 1;
    const int ss   = pp >> 1;
    const int lane = t & 31;
    const int lsel = (lane < 28) ? lane : 27;   // row element this lane carries

    const int e0 = q * 4;              // plane linear base (y*14+x), 16B aligned
    const int y0 = e0 / 14;
    const int x0 = e0 - y0 * 14;       // even, 0..12
    // only x0==12 quads cross into row y0+1 (elements 2,3 wrap to x=0,1)
    const bool cross = (x0 == 12);
    const int xo2 = cross ? 0 : x0 + 2;
    const int xo3 = cross ? 1 : x0 + 3;
    const int y1  = cross ? y0 + 1 : y0;

    const float* cen = nb + (102 + ss * 51) * 196;

    // b = cen0*cenk at this thread's quad
    const float4 c0 = *(const float4*)(cen + e0);
    const float4 ck = *(const float4*)(cen + (1 + k) * 196 + e0);
    const float b0 = c0.x * ck.x, b1 = c0.y * ck.y, b2 = c0.z * ck.z, b3 = c0.w * ck.w;

    __syncthreads();

    float* opp = out + (size_t)((pp * 32 + n) * 20 + k) * 38416 + e0;
    const float* Rcc = &R_s[cc][0][0];

    #pragma unroll
    for (int jb = 0; jb < 14; jb += 7) {
        // register-cache Lsy quads for 7 j's, reused across all 7 i's
        float4 L[7];
        #pragma unroll
        for (int j = 0; j < 7; ++j)
            L[j] = *(const float4*)(cen + (37 + jb + j) * 196 + e0);

        #pragma unroll
        for (int il = 0; il < 7; ++il) {
            const int i = i0g + il;
            const float4 sx = *(const float4*)(cen + (23 + i) * 196 + e0);
            const float r0 = b0 * sx.x, r1 = b1 * sx.y, r2 = b2 * sx.z, r3 = b3 * sx.w;

            const float* Rrow = Rcc + (il * 14 + jb) * 29;
            float* orow = opp + (size_t)i * 2744 + (size_t)jb * 196;

            #pragma unroll
            for (int j = 0; j < 7; ++j) {
                const float rv = Rrow[lsel];        // 1 wavefront: 28 words, broadcast
                const float wlo = __shfl_sync(0xFFFFFFFFu, rv, y0);
                const float whi = __shfl_sync(0xFFFFFFFFu, rv, y1);
                const float v0  = __shfl_sync(0xFFFFFFFFu, rv, 14 + x0);
                const float v1  = __shfl_sync(0xFFFFFFFFu, rv, 14 + x0 + 1);
                const float v2  = __shfl_sync(0xFFFFFFFFu, rv, 14 + xo2);
                const float v3  = __shfl_sync(0xFFFFFFFFu, rv, 14 + xo3);
                float4 o;
                o.x = (wlo * v0) * (r0 * L[j].x);
                o.y = (wlo * v1) * (r1 * L[j].y);
                o.z = (whi * v2) * (r2 * L[j].z);
                o.w = (whi * v3) * (r3 * L[j].w);
                if (act) *(float4*)(orow + j * 196) = o;
                Rrow += 29;
            }
        }
    }
}

extern "C" void kernel_launch(void* const* d_in, const int* in_sizes, int n_in,
                              void* d_out, int out_size)
{
    const float* in = (const float*)d_in[0];
    float* out = (float*)d_out;
    dim3 grid(20, 32, 2);
    plnet_kernel<<<grid, 256>>>(in, out);
}

// round 3
// speedup vs baseline: 1.2234x; 1.2234x over previous
#include <cuda_runtime.h>

// PLNet expansion: out[pp][n,k,i,j,y,x] =
//   0.5*cor0[ij]*cork[ij] * cen0[yx]*cenk[yx]
//   * cor[23+y][ij] * cor[37+x][ij] * cen[23+i][yx] * cen[37+j][yx]
// cor = corner(pp&1), cen = center(pp>>1). Input (n,204,14,14):
// corner1 ch 0..50, corner2 51..101, center1 102..152, center2 153..203.
//
// Block (k=bx, n=by, i-chunk of 7 = bz), 196 threads = 4 pp x 49 quads
// (no idle lanes). Thread owns an aligned float4 quad of the (y,x) plane.
// cen side fully register-resident (L[7] quads reused over 7 i's).

__global__ __launch_bounds__(196)
void plnet_kernel(const float* __restrict__ in, float* __restrict__ out)
{
    const int k  = blockIdx.x;       // 0..19
    const int n  = blockIdx.y;       // 0..31
    const int i0 = blockIdx.z * 7;   // 0 or 7
    const int t  = threadIdx.x;

    // W[cc][rij][y] = 0.5*cor0*cork*cor[23+y] ; V[cc][rij][x] = cor[37+x]
    // rij = i_local*14 + j, 0..97
    __shared__ float W_s[2][98][14];
    __shared__ float V_s[2][98][14];
    __shared__ float a_s[2][98];

    const float* nb = in + n * (204 * 196);

    if (t < 196) {
        const int cc  = t / 98;
        const int rij = t - cc * 98;
        const int ij  = i0 * 14 + rij;
        const float* cor = nb + cc * (51 * 196);
        a_s[cc][rij] = 0.5f * cor[ij] * cor[(1 + k) * 196 + ij];
    }
    __syncthreads();

    // build W,V: rij fastest -> coalesced LDG
    for (int idx = t; idx < 2 * 98 * 28; idx += 196) {
        const int rij = idx % 98;
        const int r2  = idx / 98;
        const int c   = r2 % 28;
        const int cc  = r2 / 28;
        const int ij  = i0 * 14 + rij;
        const float* cor = nb + cc * (51 * 196);
        if (c < 14) W_s[cc][rij][c] = a_s[cc][rij] * cor[(23 + c) * 196 + ij];
        else        V_s[cc][rij][c - 14] = cor[(37 + (c - 14)) * 196 + ij];
    }

    // per-thread setup
    const int pp = t / 49;
    const int q  = t - pp * 49;
    const int cc = pp & 1;
    const int ss = pp >> 1;
    const int e0 = q * 4;            // plane base (y*14+x), 16B aligned
    const int y0 = e0 / 14;
    const int x0 = e0 - y0 * 14;     // even, 0..12
    const bool cross = (x0 == 12);   // elements 2,3 wrap to (y0+1, x=0,1)
    const int vxo = cross ? 0 : x0 + 2;  // even -> aligned float2
    const int y1  = cross ? y0 + 1 : y0;

    const float* cen = nb + (102 + ss * 51) * 196;
    const float4 c0 = *(const float4*)(cen + e0);
    const float4 ck = *(const float4*)(cen + (1 + k) * 196 + e0);
    const float b0 = c0.x * ck.x, b1 = c0.y * ck.y, b2 = c0.z * ck.z, b3 = c0.w * ck.w;

    __syncthreads();

    float* opp = out + (size_t)((pp * 32 + n) * 20 + k) * 38416
                     + (size_t)i0 * 2744 + e0;
    const float (*Wc)[14] = W_s[cc];
    const float (*Vc)[14] = V_s[cc];

    #pragma unroll
    for (int jb = 0; jb < 14; jb += 7) {
        float4 L[7];
        #pragma unroll
        for (int j = 0; j < 7; ++j)
            L[j] = *(const float4*)(cen + (37 + jb + j) * 196 + e0);

        #pragma unroll 1
        for (int il = 0; il < 7; ++il) {
            const float4 sx = *(const float4*)(cen + (23 + i0 + il) * 196 + e0);
            const float r0 = b0 * sx.x, r1 = b1 * sx.y, r2 = b2 * sx.z, r3 = b3 * sx.w;

            const int rij0 = il * 14 + jb;
            float* orow = opp + (size_t)il * 2744 + (size_t)jb * 196;

            #pragma unroll
            for (int j = 0; j < 7; ++j) {
                const float* wr = Wc[rij0 + j];
                const float* vr = Vc[rij0 + j];
                const float wlo = wr[y0];
                const float whi = wr[y1];
                const float2 vA = *(const float2*)(vr + x0);   // aligned: x0 even
                const float2 vB = *(const float2*)(vr + vxo);  // aligned: vxo even
                float4 o;
                o.x = (wlo * vA.x) * (r0 * L[j].x);
                o.y = (wlo * vA.y) * (r1 * L[j].y);
                o.z = (whi * vB.x) * (r2 * L[j].z);
                o.w = (whi * vB.y) * (r3 * L[j].w);
                __stcs((float4*)(orow + j * 196), o);
            }
        }
    }
}

extern "C" void kernel_launch(void* const* d_in, const int* in_sizes, int n_in,
                              void* d_out, int out_size)
{
    const float* in = (const float*)d_in[0];
    float* out = (float*)d_out;
    dim3 grid(20, 32, 2);
    plnet_kernel<<<grid, 196>>>(in, out);
}

// round 4
// speedup vs baseline: 1.3322x; 1.0889x over previous
#include <cuda_runtime.h>

// PLNet expansion: out[pp][n,k,i,j,y,x] =
//   0.5*cor0[ij]*cork[ij] * cen0[yx]*cenk[yx]
//   * cor[23+y][ij] * cor[37+x][ij] * cen[23+i][yx] * cen[37+j][yx]
// cor = corner(pp&1), cen = center(pp>>1).
// Input layout (n, 204, 14, 14): corner1 ch 0..50, corner2 51..101,
// center1 102..152, center2 153..203.
//
// R1 structure (74 us) + ONE change: V loads as aligned LDS.64 pairs.
// Block (k=bx, n=by, ichunk=bz covers i in {2bz, 2bz+1}), 196 threads.
// Thread t: pp = t/49, q = t%49 (float4 quad of the 196-elem (y,x) plane).

__global__ __launch_bounds__(196)
void plnet_kernel(const float* __restrict__ in, float* __restrict__ out)
{
    const int k  = blockIdx.x;   // 0..19
    const int n  = blockIdx.y;   // 0..31
    const int i0 = blockIdx.z * 2;  // i chunk start (0,2,...,12)
    const int t  = threadIdx.x;

    // W[cc][rij][y] = 0.5*cor0*cork*cor[23+y] at ij = i0*14+rij  (rij 0..27)
    // V[cc][rij][x] = cor[37+x] at same ij. Row stride 14 floats = 56 B (8B-mult).
    __shared__ float W_s[2 * 28 * 14];
    __shared__ float V_s[2 * 28 * 14];
    __shared__ float a_s[2 * 28];

    const float* nb = in + n * (204 * 196);

    // ---- precompute a (2 cor x 28 ij rows) ----
    if (t < 56) {
        const int cc  = t / 28;
        const int rij = t - cc * 28;
        const int ij  = i0 * 14 + rij;
        const float* cor = nb + cc * (51 * 196);
        a_s[t] = 0.5f * cor[ij] * cor[(1 + k) * 196 + ij];
    }
    __syncthreads();

    // ---- fill W,V (coalesced gmem reads: rij fastest) ----
    #pragma unroll
    for (int idx = 0; idx < 784; idx += 196) {
        const int id  = idx + t;
        const int rij = id % 28;
        const int tmp = id / 28;        // 0..27
        const int y   = tmp % 14;
        const int cc  = tmp / 14;
        const int ij  = i0 * 14 + rij;
        const float* cor = nb + cc * (51 * 196);
        W_s[cc * 392 + rij * 14 + y] = a_s[cc * 28 + rij] * cor[(23 + y) * 196 + ij];
        V_s[cc * 392 + rij * 14 + y] = cor[(37 + y) * 196 + ij];
    }

    // ---- per-thread setup ----
    const int pp = t / 49;          // output tensor 0..3
    const int q  = t - pp * 49;     // quad index in plane
    const int cc = pp & 1;          // corner select
    const int ss = pp >> 1;         // center select
    const int e0 = q * 4;           // plane linear element base (y*14+x)
    const int y0 = e0 / 14;
    const int x0 = e0 - y0 * 14;    // even, <=12

    const float* cen = nb + (102 + ss * 51) * 196;

    // b[e] = cen0*cenk at plane elements e0..e0+3 (aligned float4)
    const float4 c0 = *(const float4*)(cen + e0);
    const float4 ck = *(const float4*)(cen + (1 + k) * 196 + e0);
    const float bx = c0.x * ck.x, by = c0.y * ck.y, bz = c0.z * ck.z, bw = c0.w * ck.w;

    // only x0==12 quads cross into row y0+1 (elements 2,3 wrap to x=0,1)
    const bool cross = (x0 == 12);
    const int vxo = cross ? 0 : x0 + 2;   // even -> 8B-aligned float2
    const int y1  = cross ? y0 + 1 : y0;

    __syncthreads();

    float* op = out + (size_t)((pp * 32 + n) * 20 + k) * 38416
                    + (size_t)i0 * (14 * 196) + e0;
    const float* Wc = W_s + cc * 392;
    const float* Vc = V_s + cc * 392;

    // j in two halves of 7 so Lsy register cache stays at 28 regs
    #pragma unroll
    for (int jb = 0; jb < 14; jb += 7) {
        float4 L[7];
        #pragma unroll
        for (int j = 0; j < 7; ++j)
            L[j] = *(const float4*)(cen + (37 + jb + j) * 196 + e0);

        #pragma unroll
        for (int il = 0; il < 2; ++il) {
            const int i = i0 + il;
            const float4 sx = *(const float4*)(cen + (23 + i) * 196 + e0);
            const float r0 = bx * sx.x, r1 = by * sx.y, r2 = bz * sx.z, r3 = bw * sx.w;

            const float* Wr = Wc + il * 196;   // (il*14 + j)*14
            const float* Vr = Vc + il * 196;
            float* orow = op + (size_t)il * (14 * 196) + (size_t)jb * 196;

            #pragma unroll
            for (int j = 0; j < 7; ++j) {
                const float* wr = Wr + (jb + j) * 14;
                const float* vr = Vr + (jb + j) * 14;
                const float wlo = wr[y0];
                const float whi = wr[y1];
                const float2 vA = *(const float2*)(vr + x0);   // aligned (x0 even)
                const float2 vB = *(const float2*)(vr + vxo);  // aligned (vxo even)
                float4 o;
                o.x = (wlo * vA.x) * (r0 * L[j].x);
                o.y = (wlo * vA.y) * (r1 * L[j].y);
                o.z = (whi * vB.x) * (r2 * L[j].z);
                o.w = (whi * vB.y) * (r3 * L[j].w);
                *(float4*)(orow + j * 196) = o;
            }
        }
    }
}

extern "C" void kernel_launch(void* const* d_in, const int* in_sizes, int n_in,
                              void* d_out, int out_size)
{
    const float* in = (const float*)d_in[0];
    float* out = (float*)d_out;
    dim3 grid(20, 32, 7);
    plnet_kernel<<<grid, 196>>>(in, out);
}